// round 11
// baseline (speedup 1.0000x reference)
#include <cuda_runtime.h>

// Problem constants (fixed by the reference)
#define NROWS 8192
#define MM    128
#define DZ    128
#define DX    128
#define HH    4

#define THREADS 256
#define WARPS   8
#define R       4                       // rows per warp
#define ROWS_PER_BLK (WARPS * R)        // 32
#define NBLK (NROWS / ROWS_PER_BLK)     // 256

// Cross-block scratch + flag (zero-initialized at module load; kernel
// self-resets flag/done at the end of every launch so graph replays work).
__device__ float4 g_xWb[MM];
__device__ int    g_flag;
__device__ int    g_done;

__global__ __launch_bounds__(THREADS)
void fused(const float* __restrict__ z,
           const float* __restrict__ x,
           const float* __restrict__ W,
           const float* __restrict__ b,
           float* __restrict__ out) {
    const int tid  = threadIdx.x;
    const int lane = tid & 31;
    const int warp = tid >> 5;
    const float4* __restrict__ W4 = reinterpret_cast<const float4*>(W);

    // ---------------- Block 0: compute xWb, publish flag ----------------
    if (blockIdx.x == 0) {
        __shared__ float4 s_part[2][MM];
        const int m = tid & (MM - 1);
        const int half = tid >> 7;               // 0 or 1 (d-range halves)
        float a0 = 0.f, a1 = 0.f, a2 = 0.f, a3 = 0.f;
#pragma unroll 8
        for (int j = 0; j < 64; j++) {
            int d = half * 64 + j;
            float xv = x[d * MM + m];
            float4 w = W4[DZ + d];
            a0 = fmaf(xv, w.x, a0);
            a1 = fmaf(xv, w.y, a1);
            a2 = fmaf(xv, w.z, a2);
            a3 = fmaf(xv, w.w, a3);
        }
        s_part[half][m] = make_float4(a0, a1, a2, a3);
        __syncthreads();
        if (tid < MM) {
            float4 p = s_part[0][tid];
            float4 q = s_part[1][tid];
            float4 bb = *reinterpret_cast<const float4*>(b);
            g_xWb[tid] = make_float4(p.x + q.x + bb.x, p.y + q.y + bb.y,
                                     p.z + q.z + bb.z, p.w + q.w + bb.w);
        }
        __syncthreads();
        if (tid == 0) {
            __threadfence();
            atomicExch(&g_flag, 1);
        }
    }

    // ---------------- zW for this warp's 4 rows (overlaps block 0) -------
    const int n0 = blockIdx.x * ROWS_PER_BLK + warp * R;

    float4 w0 = W4[4 * lane + 0];
    float4 w1 = W4[4 * lane + 1];
    float4 w2 = W4[4 * lane + 2];
    float4 w3 = W4[4 * lane + 3];

    float4 zv[R];
#pragma unroll
    for (int r = 0; r < R; r++)
        zv[r] = reinterpret_cast<const float4*>(z + (size_t)(n0 + r) * DZ)[lane];

    const bool p1 = (lane & 1) != 0;
    const bool p2 = (lane & 2) != 0;
    float4 s[R];
#pragma unroll
    for (int r = 0; r < R; r++) {
        float a0 = zv[r].x * w0.x + zv[r].y * w1.x + zv[r].z * w2.x + zv[r].w * w3.x;
        float a1 = zv[r].x * w0.y + zv[r].y * w1.y + zv[r].z * w2.y + zv[r].w * w3.y;
        float a2 = zv[r].x * w0.z + zv[r].y * w1.z + zv[r].z * w2.z + zv[r].w * w3.z;
        float a3 = zv[r].x * w0.w + zv[r].y * w1.w + zv[r].z * w2.w + zv[r].w * w3.w;

        // Packed reduction: merge 4 accumulators into lanes (head = lane&3),
        // then 3 butterflies, then broadcast the 4 head sums.
        float snd01 = p1 ? a0 : a1;
        float rcv01 = __shfl_xor_sync(0xffffffffu, snd01, 1);
        float u = (p1 ? a1 : a0) + rcv01;
        float snd23 = p1 ? a2 : a3;
        float rcv23 = __shfl_xor_sync(0xffffffffu, snd23, 1);
        float v = (p1 ? a3 : a2) + rcv23;
        float snduv = p2 ? u : v;
        float rcvuv = __shfl_xor_sync(0xffffffffu, snduv, 2);
        float w = (p2 ? v : u) + rcvuv;
        w += __shfl_xor_sync(0xffffffffu, w, 4);
        w += __shfl_xor_sync(0xffffffffu, w, 8);
        w += __shfl_xor_sync(0xffffffffu, w, 16);
        s[r].x = __shfl_sync(0xffffffffu, w, 0);
        s[r].y = __shfl_sync(0xffffffffu, w, 1);
        s[r].z = __shfl_sync(0xffffffffu, w, 2);
        s[r].w = __shfl_sync(0xffffffffu, w, 3);
    }

    // ---------------- Wait for xWb, then store ---------------------------
    if (lane == 0) {
        while (atomicAdd(&g_flag, 0) == 0) __nanosleep(40);
    }
    __syncwarp();
    __threadfence();  // acquire: order xWb reads after the flag observation

    float4 xw0 = __ldcg(&g_xWb[lane]);
    float4 xw1 = __ldcg(&g_xWb[lane + 32]);
    float4 xw2 = __ldcg(&g_xWb[lane + 64]);
    float4 xw3 = __ldcg(&g_xWb[lane + 96]);

#pragma unroll
    for (int r = 0; r < R; r++) {
        float4* __restrict__ out4 =
            reinterpret_cast<float4*>(out) + (size_t)(n0 + r) * MM;
        float4 o;
        o.x = fmaxf(s[r].x + xw0.x, 0.f); o.y = fmaxf(s[r].y + xw0.y, 0.f);
        o.z = fmaxf(s[r].z + xw0.z, 0.f); o.w = fmaxf(s[r].w + xw0.w, 0.f);
        out4[lane] = o;
        o.x = fmaxf(s[r].x + xw1.x, 0.f); o.y = fmaxf(s[r].y + xw1.y, 0.f);
        o.z = fmaxf(s[r].z + xw1.z, 0.f); o.w = fmaxf(s[r].w + xw1.w, 0.f);
        out4[lane + 32] = o;
        o.x = fmaxf(s[r].x + xw2.x, 0.f); o.y = fmaxf(s[r].y + xw2.y, 0.f);
        o.z = fmaxf(s[r].z + xw2.z, 0.f); o.w = fmaxf(s[r].w + xw2.w, 0.f);
        out4[lane + 64] = o;
        o.x = fmaxf(s[r].x + xw3.x, 0.f); o.y = fmaxf(s[r].y + xw3.y, 0.f);
        o.z = fmaxf(s[r].z + xw3.z, 0.f); o.w = fmaxf(s[r].w + xw3.w, 0.f);
        out4[lane + 96] = o;
    }

    // ---------------- Self-reset for graph replays -----------------------
    // Barrier first: every warp of this block has passed the spin, so once
    // all blocks arrive it is safe to clear the flag.
    __syncthreads();
    if (tid == 0) {
        int old = atomicAdd(&g_done, 1);
        if (old == NBLK - 1) {
            g_done = 0;
            __threadfence();
            g_flag = 0;
        }
    }
}

// ---------------------------------------------------------------------------
// Launch. Inputs (metadata order): z [N*DZ], x [DX*M], W [(DZ+DX)*H], b [H].
// Output: float32 [N*M*H].
// ---------------------------------------------------------------------------
extern "C" void kernel_launch(void* const* d_in, const int* in_sizes, int n_in,
                              void* d_out, int out_size) {
    const float* z = (const float*)d_in[0];
    const float* x = (const float*)d_in[1];
    const float* W = (const float*)d_in[2];
    const float* b = (const float*)d_in[3];
    float* out = (float*)d_out;

    fused<<<NBLK, THREADS>>>(z, x, W, b, out);
}

// round 14
// speedup vs baseline: 1.3208x; 1.3208x over previous
#include <cuda_runtime.h>

// Problem constants (fixed by the reference)
#define NROWS 8192
#define MM    128
#define DZ    128
#define DX    128
#define HH    4

#define THREADS 256
#define WARPS   8
#define R       4                        // rows per warp
#define ROWS_PER_BLK (WARPS * R)         // 32
#define NBLK (NROWS / ROWS_PER_BLK)      // 256

__global__ __launch_bounds__(THREADS)
void fused(const float* __restrict__ z,
           const float* __restrict__ x,
           const float* __restrict__ W,
           const float* __restrict__ b,
           float* __restrict__ out) {
    __shared__ float4 s_part[2][MM];     // xWb partials (bias folded in half 0)

    const int tid  = threadIdx.x;
    const int lane = tid & 31;
    const int warp = tid >> 5;
    const float4* __restrict__ W4 = reinterpret_cast<const float4*>(W);
    const int n0 = blockIdx.x * ROWS_PER_BLK + warp * R;

    // ---- Hoist the long-latency z loads (DRAM) to the very top ----------
    float4 zv[R];
#pragma unroll
    for (int r = 0; r < R; r++)
        zv[r] = reinterpret_cast<const float4*>(z + (size_t)(n0 + r) * DZ)[lane];

    // ---- Phase A: xWb partials. thread = (m, d-half), 64 FMAs x 4 heads --
    {
        const int m = tid & (MM - 1);
        const int half = tid >> 7;       // 0 or 1
        float a0, a1, a2, a3;
        if (half == 0) {                 // fold bias into half 0
            float4 bb = *reinterpret_cast<const float4*>(b);
            a0 = bb.x; a1 = bb.y; a2 = bb.z; a3 = bb.w;
        } else {
            a0 = a1 = a2 = a3 = 0.f;
        }
#pragma unroll 8
        for (int j = 0; j < 64; j++) {
            int d = half * 64 + j;
            float xv = x[d * MM + m];
            float4 w = W4[DZ + d];
            a0 = fmaf(xv, w.x, a0);
            a1 = fmaf(xv, w.y, a1);
            a2 = fmaf(xv, w.z, a2);
            a3 = fmaf(xv, w.w, a3);
        }
        s_part[half][m] = make_float4(a0, a1, a2, a3);
    }

    // ---- Phase B: zW per warp (4 rows), packed reduce -> broadcast regs --
    float4 w0 = W4[4 * lane + 0];
    float4 w1 = W4[4 * lane + 1];
    float4 w2 = W4[4 * lane + 2];
    float4 w3 = W4[4 * lane + 3];

    const bool p1 = (lane & 1) != 0;
    const bool p2 = (lane & 2) != 0;
    float4 s[R];
#pragma unroll
    for (int r = 0; r < R; r++) {
        float a0 = zv[r].x * w0.x + zv[r].y * w1.x + zv[r].z * w2.x + zv[r].w * w3.x;
        float a1 = zv[r].x * w0.y + zv[r].y * w1.y + zv[r].z * w2.y + zv[r].w * w3.y;
        float a2 = zv[r].x * w0.z + zv[r].y * w1.z + zv[r].z * w2.z + zv[r].w * w3.z;
        float a3 = zv[r].x * w0.w + zv[r].y * w1.w + zv[r].z * w2.w + zv[r].w * w3.w;

        // Merge 4 head accumulators into lanes (head = lane&3): 3 exchanges,
        // then 3 butterflies, then broadcast the 4 head sums. 10 SHFL total.
        float snd01 = p1 ? a0 : a1;
        float rcv01 = __shfl_xor_sync(0xffffffffu, snd01, 1);
        float u = (p1 ? a1 : a0) + rcv01;
        float snd23 = p1 ? a2 : a3;
        float rcv23 = __shfl_xor_sync(0xffffffffu, snd23, 1);
        float v = (p1 ? a3 : a2) + rcv23;
        float snduv = p2 ? u : v;
        float rcvuv = __shfl_xor_sync(0xffffffffu, snduv, 2);
        float t = (p2 ? v : u) + rcvuv;
        t += __shfl_xor_sync(0xffffffffu, t, 4);
        t += __shfl_xor_sync(0xffffffffu, t, 8);
        t += __shfl_xor_sync(0xffffffffu, t, 16);
        s[r].x = __shfl_sync(0xffffffffu, t, 0);
        s[r].y = __shfl_sync(0xffffffffu, t, 1);
        s[r].z = __shfl_sync(0xffffffffu, t, 2);
        s[r].w = __shfl_sync(0xffffffffu, t, 3);
    }

    // ---- Single barrier: xWb partials visible -----------------------------
    __syncthreads();

    // Each lane's 4 m-columns: lane, lane+32, lane+64, lane+96.
    float4 xw[4];
#pragma unroll
    for (int q = 0; q < 4; q++) {
        int m = lane + 32 * q;
        float4 pa = s_part[0][m];
        float4 pb = s_part[1][m];
        xw[q] = make_float4(pa.x + pb.x, pa.y + pb.y, pa.z + pb.z, pa.w + pb.w);
    }

    // ---- Stores: 16 coalesced STG.128 per lane, all register-sourced -----
#pragma unroll
    for (int r = 0; r < R; r++) {
        float4* __restrict__ out4 =
            reinterpret_cast<float4*>(out) + (size_t)(n0 + r) * MM;
#pragma unroll
        for (int q = 0; q < 4; q++) {
            float4 o;
            o.x = fmaxf(s[r].x + xw[q].x, 0.f);
            o.y = fmaxf(s[r].y + xw[q].y, 0.f);
            o.z = fmaxf(s[r].z + xw[q].z, 0.f);
            o.w = fmaxf(s[r].w + xw[q].w, 0.f);
            out4[lane + 32 * q] = o;
        }
    }
}

// ---------------------------------------------------------------------------
// Launch. Inputs (metadata order): z [N*DZ], x [DX*M], W [(DZ+DX)*H], b [H].
// Output: float32 [N*M*H].
// ---------------------------------------------------------------------------
extern "C" void kernel_launch(void* const* d_in, const int* in_sizes, int n_in,
                              void* d_out, int out_size) {
    const float* z = (const float*)d_in[0];
    const float* x = (const float*)d_in[1];
    const float* W = (const float*)d_in[2];
    const float* b = (const float*)d_in[3];
    float* out = (float*)d_out;

    fused<<<NBLK, THREADS>>>(z, x, W, b, out);
}